// round 16
// baseline (speedup 1.0000x reference)
#include <cuda_runtime.h>
#include <cstdint>

// YOLO v1 loss: pred/target (2048,14,14,30) fp32 -> scalar fp32.
// Persistent warp-specialized pipeline, 1 block/SM, 64-cell stages, DEPTH=12.
// Warp 8 = TMA producer. Consumers: 4 groups of 2 warps (group g = warps
// {g, g+4}, both on SMSP g); group g handles tiles it ≡ g (mod 4).
// Epilogue: ONE packed atomic per block (sum low 56 bits, counter high 8).

#define TPB 288                   // 8 consumer warps + 1 producer warp
#define CH  30
#define CELLS_PER_TILE 64
#define TILE_BYTES (CELLS_PER_TILE * CH * 4)   // 7680 per tensor
#define STAGE_BYTES (2 * TILE_BYTES)           // 15360 (pred + tgt)
#define STAGE_FLOATS (STAGE_BYTES / 4)
#define DEPTH 12
#define GRID 148
#define SMEM_BYTES (DEPTH * STAGE_BYTES + 256) // 184576
#define SCALE_BITS 24
#define CNT_SHIFT 56
#define SUM_MASK ((1ULL << CNT_SHIFT) - 1ULL)

__device__ unsigned long long g_acc = 0ULL;

__device__ __forceinline__ uint32_t smem_u32(const void* p) {
    uint32_t a;
    asm("{ .reg .u64 t; cvta.to.shared.u64 t, %1; cvt.u32.u64 %0, t; }"
        : "=r"(a) : "l"(p));
    return a;
}

__device__ __forceinline__ void mbar_wait(uint32_t mbar_a, uint32_t parity) {
    uint32_t done;
    asm volatile(
        "{\n\t"
        ".reg .pred p;\n\t"
        "mbarrier.try_wait.parity.acquire.cta.shared::cta.b64 p, [%1], %2;\n\t"
        "selp.b32 %0, 1, 0, p;\n\t"
        "}"
        : "=r"(done) : "r"(mbar_a), "r"(parity) : "memory");
    if (!done) {
        asm volatile(
            "{\n\t"
            ".reg .pred P1;\n\t"
            "W_%=:\n\t"
            "mbarrier.try_wait.parity.acquire.cta.shared::cta.b64 P1, [%0], %1, 0x989680;\n\t"
            "@P1 bra.uni D_%=;\n\t"
            "bra.uni W_%=;\n\t"
            "D_%=:\n\t"
            "}"
            :: "r"(mbar_a), "r"(parity) : "memory");
    }
}

__global__ void __launch_bounds__(TPB) yolo_fused_kernel(
    const float* __restrict__ pred,
    const float* __restrict__ tgt,
    float* __restrict__ out,
    int ntiles, float invN)
{
    extern __shared__ char smem[];
    float* buf = reinterpret_cast<float*>(smem);
    // mbar layout after buffers: full[DEPTH] then empty[DEPTH]
    const uint32_t full0  = smem_u32(smem + DEPTH * STAGE_BYTES);
    const uint32_t empty0 = full0 + 8u * DEPTH;

    const int tid  = threadIdx.x;
    const int wid  = tid >> 5;
    const int lane = tid & 31;

    if (tid == 0) {
        #pragma unroll
        for (int s = 0; s < DEPTH; s++) {
            asm volatile("mbarrier.init.shared.b64 [%0], %1;"
                         :: "r"(full0 + 8u * s), "r"(1) : "memory");
            asm volatile("mbarrier.init.shared.b64 [%0], %1;"
                         :: "r"(empty0 + 8u * s), "r"(2) : "memory");
        }
    }
    __syncthreads();

    float acc = 0.0f;

    if (wid == 8) {
        // ---------------- Producer warp (lane 0 only) ----------------
        if (lane == 0) {
            int stage = 0;
            uint32_t eparity = 1u;   // fresh-barrier first wait passes
            for (int tile = blockIdx.x; tile < ntiles; tile += GRID) {
                mbar_wait(empty0 + 8u * stage, eparity);

                uint32_t mb  = full0 + 8u * stage;
                uint32_t dst = smem_u32(buf) + (uint32_t)(stage * STAGE_BYTES);
                asm volatile("mbarrier.arrive.expect_tx.shared.b64 _, [%0], %1;"
                             :: "r"(mb), "r"((uint32_t)STAGE_BYTES) : "memory");
                const float* pg = pred + (long long)tile * (CELLS_PER_TILE * CH);
                const float* tg = tgt  + (long long)tile * (CELLS_PER_TILE * CH);
                asm volatile(
                    "cp.async.bulk.shared::cta.global.mbarrier::complete_tx::bytes "
                    "[%0], [%1], %2, [%3];"
                    :: "r"(dst), "l"(pg), "r"((uint32_t)TILE_BYTES), "r"(mb) : "memory");
                asm volatile(
                    "cp.async.bulk.shared::cta.global.mbarrier::complete_tx::bytes "
                    "[%0], [%1], %2, [%3];"
                    :: "r"(dst + TILE_BYTES), "l"(tg), "r"((uint32_t)TILE_BYTES), "r"(mb) : "memory");

                if (++stage == DEPTH) { stage = 0; eparity ^= 1u; }
            }
        }
    } else {
        // -------- Consumer warps: 4 groups of 2 (same-SMSP pairs) --------
        const float inv14 = 1.0f / 14.0f;
        const int group = wid & 3;                // SMSP id
        const int sub   = wid >> 2;               // 0 or 1 within group
        const int cell  = sub * 32 + lane;        // cell within each 64-cell tile

        for (int it = group; ; it += 4) {
            int tile = blockIdx.x + it * GRID;
            if (tile >= ntiles) break;
            int stage = it % DEPTH;
            uint32_t fparity = (uint32_t)((it / DEPTH) & 1);
            mbar_wait(full0 + 8u * stage, fparity);

            const float* p = buf + stage * STAGE_FLOATS + cell * CH;
            const float* t = p + CELLS_PER_TILE * CH;

            float conf_t = t[4];
            float coo = (conf_t > 0.0f) ? 1.0f : 0.0f;
            float noo = (conf_t == 0.0f) ? 1.0f : 0.0f;

            float d4 = p[4] - t[4];
            float d9 = p[9] - t[9];
            float noo_loss = d4 * d4 + d9 * d9;

            float cls = 0.0f;
            #pragma unroll
            for (int c = 10; c < 30; c++) {
                float dc = p[c] - t[c];
                cls += dc * dc;
            }

            float t0x1 = t[0] * inv14 - 0.5f * t[2];
            float t0y1 = t[1] * inv14 - 0.5f * t[3];
            float t0x2 = t[0] * inv14 + 0.5f * t[2];
            float t0y2 = t[1] * inv14 + 0.5f * t[3];
            float a2 = (t0x2 - t0x1) * (t0y2 - t0y1);

            float iou[2];
            #pragma unroll
            for (int b = 0; b < 2; b++) {
                const float* bb = p + 5 * b;
                float x1 = bb[0] * inv14 - 0.5f * bb[2];
                float y1 = bb[1] * inv14 - 0.5f * bb[3];
                float x2 = bb[0] * inv14 + 0.5f * bb[2];
                float y2 = bb[1] * inv14 + 0.5f * bb[3];
                float lx = fmaxf(x1, t0x1);
                float ly = fmaxf(y1, t0y1);
                float rx = fminf(x2, t0x2);
                float ry = fminf(y2, t0y2);
                float w = fmaxf(rx - lx, 0.0f);
                float h = fmaxf(ry - ly, 0.0f);
                float inter = w * h;
                float a1 = (x2 - x1) * (y2 - y1);
                iou[b] = inter / (a1 + a2 - inter);
            }

            int idx = (iou[1] > iou[0]) ? 1 : 0;
            float max_iou = fmaxf(iou[0], iou[1]);

            const float* pr = p + 5 * idx;
            const float* tr = t + 5 * idx;

            float dconf = pr[4] - max_iou;
            float contain = dconf * dconf;

            float dx = pr[0] - tr[0];
            float dy = pr[1] - tr[1];
            float dw = sqrtf(pr[2]) - sqrtf(tr[2]);
            float dh = sqrtf(pr[3]) - sqrtf(tr[3]);
            float loc = dx * dx + dy * dy + dw * dw + dh * dh;

            float oconf = idx ? p[4] : p[9];
            float not_contain = oconf * oconf;

            acc += coo * (5.0f * loc + 2.0f * contain + not_contain + cls)
                 + 0.5f * noo * noo_loss;

            // This warp is done reading its slice of the stage.
            __syncwarp();
            if (lane == 0)
                asm volatile("mbarrier.arrive.release.cta.shared::cta.b64 _, [%0];"
                             :: "r"(empty0 + 8u * stage) : "memory");
        }
    }

    // ---------------- Epilogue: block reduce + single packed atomic ----------
    #pragma unroll
    for (int o = 16; o > 0; o >>= 1)
        acc += __shfl_down_sync(0xffffffffu, acc, o);

    __shared__ float warpsum[8];
    if (wid < 8 && lane == 0) warpsum[wid] = acc;
    __syncthreads();

    if (tid == 0) {
        double s = 0.0;
        #pragma unroll
        for (int i = 0; i < 8; i++) s += (double)warpsum[i];

        // fixed-point contribution (all loss terms >= 0); block sums < 2^41,
        // grand total < 2^48 << 2^56, so bits [56,64) hold the block counter.
        unsigned long long q =
            (unsigned long long)__double2ll_rn(s * (double)(1 << SCALE_BITS));
        unsigned long long old =
            atomicAdd(&g_acc, q | (1ULL << CNT_SHIFT));

        if ((old >> CNT_SHIFT) == (unsigned long long)(GRID - 1)) {
            unsigned long long tot = (old & SUM_MASK) + q;
            out[0] = (float)((double)tot *
                             (1.0 / (double)(1 << SCALE_BITS)) * (double)invN);
            g_acc = 0ULL;   // reset for next graph replay
        }
    }
}

extern "C" void kernel_launch(void* const* d_in, const int* in_sizes, int n_in,
                              void* d_out, int out_size)
{
    const float* pred = (const float*)d_in[0];
    const float* tgt  = (const float*)d_in[1];
    float* out = (float*)d_out;

    int total = in_sizes[0];               // 2048*14*14*30
    int cells = total / CH;                // 401408 (= 6272 * 64 exactly)
    int N = cells / (14 * 14);             // 2048
    int ntiles = cells / CELLS_PER_TILE;   // 6272

    cudaFuncSetAttribute(yolo_fused_kernel,
                         cudaFuncAttributeMaxDynamicSharedMemorySize,
                         SMEM_BYTES);

    yolo_fused_kernel<<<GRID, TPB, SMEM_BYTES>>>(pred, tgt, out, ntiles,
                                                 1.0f / (float)N);
}

// round 17
// speedup vs baseline: 1.1775x; 1.1775x over previous
#include <cuda_runtime.h>
#include <cstdint>

// YOLO v1 loss: pred/target (2048,14,14,30) fp32 -> scalar fp32.  FINAL FORM.
// Persistent warp-specialized pipeline, 1 block/SM, 128-cell stages, DEPTH=6.
// Warp 8 = TMA producer (relaxed empty-waits: post-wait ops are async-proxy
// only). Consumer warps 0-3 take even tiles (stages 0,2,4); warps 4-7 take
// odd tiles (stages 1,3,5). Epilogue: ONE packed atomic per block
// (fixed-point sum in low 56 bits, completion counter in high 8 bits).

#define TPB 288                   // 8 consumer warps + 1 producer warp
#define CH  30
#define CELLS_PER_TILE 128
#define TILE_BYTES (CELLS_PER_TILE * CH * 4)   // 15360 per tensor
#define STAGE_BYTES (2 * TILE_BYTES)           // 30720 (pred + tgt)
#define STAGE_FLOATS (STAGE_BYTES / 4)
#define DEPTH 6
#define GRID 148
#define SMEM_BYTES (DEPTH * STAGE_BYTES + 128) // 184448
#define SCALE_BITS 24
#define CNT_SHIFT 56
#define SUM_MASK ((1ULL << CNT_SHIFT) - 1ULL)

__device__ unsigned long long g_acc = 0ULL;

__device__ __forceinline__ uint32_t smem_u32(const void* p) {
    uint32_t a;
    asm("{ .reg .u64 t; cvta.to.shared.u64 t, %1; cvt.u32.u64 %0, t; }"
        : "=r"(a) : "l"(p));
    return a;
}

// Acquire wait: consumers (generic LDS follows).
__device__ __forceinline__ void mbar_wait_acq(uint32_t mbar_a, uint32_t parity) {
    uint32_t done;
    asm volatile(
        "{\n\t"
        ".reg .pred p;\n\t"
        "mbarrier.try_wait.parity.acquire.cta.shared::cta.b64 p, [%1], %2;\n\t"
        "selp.b32 %0, 1, 0, p;\n\t"
        "}"
        : "=r"(done) : "r"(mbar_a), "r"(parity) : "memory");
    if (!done) {
        asm volatile(
            "{\n\t"
            ".reg .pred P1;\n\t"
            "W_%=:\n\t"
            "mbarrier.try_wait.parity.acquire.cta.shared::cta.b64 P1, [%0], %1, 0x989680;\n\t"
            "@P1 bra.uni D_%=;\n\t"
            "bra.uni W_%=;\n\t"
            "D_%=:\n\t"
            "}"
            :: "r"(mbar_a), "r"(parity) : "memory");
    }
}

// Relaxed wait: producer only (post-wait SMEM accesses are all async-proxy:
// expect_tx + cp.async.bulk, ordered by their own proxy fencing).
__device__ __forceinline__ void mbar_wait_rlx(uint32_t mbar_a, uint32_t parity) {
    uint32_t done;
    asm volatile(
        "{\n\t"
        ".reg .pred p;\n\t"
        "mbarrier.try_wait.parity.relaxed.cta.shared::cta.b64 p, [%1], %2, 0x989680;\n\t"
        "selp.b32 %0, 1, 0, p;\n\t"
        "}"
        : "=r"(done) : "r"(mbar_a), "r"(parity) : "memory");
    if (!done) {
        asm volatile(
            "{\n\t"
            ".reg .pred P1;\n\t"
            "W_%=:\n\t"
            "mbarrier.try_wait.parity.relaxed.cta.shared::cta.b64 P1, [%0], %1, 0x989680;\n\t"
            "@P1 bra.uni D_%=;\n\t"
            "bra.uni W_%=;\n\t"
            "D_%=:\n\t"
            "}"
            :: "r"(mbar_a), "r"(parity) : "memory");
    }
}

__global__ void __launch_bounds__(TPB) yolo_fused_kernel(
    const float* __restrict__ pred,
    const float* __restrict__ tgt,
    float* __restrict__ out,
    int ntiles, float invN)
{
    extern __shared__ char smem[];
    float* buf = reinterpret_cast<float*>(smem);
    // mbar layout after buffers: full[DEPTH] then empty[DEPTH]
    const uint32_t full0  = smem_u32(smem + DEPTH * STAGE_BYTES);
    const uint32_t empty0 = full0 + 8u * DEPTH;

    const int tid  = threadIdx.x;
    const int wid  = tid >> 5;
    const int lane = tid & 31;

    if (tid == 0) {
        #pragma unroll
        for (int s = 0; s < DEPTH; s++) {
            asm volatile("mbarrier.init.shared.b64 [%0], %1;"
                         :: "r"(full0 + 8u * s), "r"(1) : "memory");
            asm volatile("mbarrier.init.shared.b64 [%0], %1;"
                         :: "r"(empty0 + 8u * s), "r"(4) : "memory");
        }
    }
    __syncthreads();

    float acc = 0.0f;

    if (wid == 8) {
        // ---------------- Producer warp (lane 0 only) ----------------
        if (lane == 0) {
            int stage = 0;
            uint32_t eparity = 1u;   // fresh-barrier first wait passes
            for (int tile = blockIdx.x; tile < ntiles; tile += GRID) {
                mbar_wait_rlx(empty0 + 8u * stage, eparity);

                uint32_t mb  = full0 + 8u * stage;
                uint32_t dst = smem_u32(buf) + (uint32_t)(stage * STAGE_BYTES);
                asm volatile("mbarrier.arrive.expect_tx.shared.b64 _, [%0], %1;"
                             :: "r"(mb), "r"((uint32_t)STAGE_BYTES) : "memory");
                const float* pg = pred + (long long)tile * (CELLS_PER_TILE * CH);
                const float* tg = tgt  + (long long)tile * (CELLS_PER_TILE * CH);
                asm volatile(
                    "cp.async.bulk.shared::cta.global.mbarrier::complete_tx::bytes "
                    "[%0], [%1], %2, [%3];"
                    :: "r"(dst), "l"(pg), "r"((uint32_t)TILE_BYTES), "r"(mb) : "memory");
                asm volatile(
                    "cp.async.bulk.shared::cta.global.mbarrier::complete_tx::bytes "
                    "[%0], [%1], %2, [%3];"
                    :: "r"(dst + TILE_BYTES), "l"(tg), "r"((uint32_t)TILE_BYTES), "r"(mb) : "memory");

                if (++stage == DEPTH) { stage = 0; eparity ^= 1u; }
            }
        }
    } else {
        // ------------- Consumer warps: two groups of 4 -------------
        const float inv14 = 1.0f / 14.0f;
        const int group = wid >> 2;               // 0 or 1
        const int cell = (wid & 3) * 32 + lane;   // cell within each tile

        for (int it = group; ; it += 2) {
            int tile = blockIdx.x + it * GRID;
            if (tile >= ntiles) break;
            int stage = it % DEPTH;
            uint32_t fparity = (uint32_t)((it / DEPTH) & 1);
            mbar_wait_acq(full0 + 8u * stage, fparity);

            const float* p = buf + stage * STAGE_FLOATS + cell * CH;
            const float* t = p + CELLS_PER_TILE * CH;

            float conf_t = t[4];
            float coo = (conf_t > 0.0f) ? 1.0f : 0.0f;
            float noo = (conf_t == 0.0f) ? 1.0f : 0.0f;

            float d4 = p[4] - t[4];
            float d9 = p[9] - t[9];
            float noo_loss = d4 * d4 + d9 * d9;

            float cls = 0.0f;
            #pragma unroll
            for (int c = 10; c < 30; c++) {
                float dc = p[c] - t[c];
                cls += dc * dc;
            }

            float t0x1 = t[0] * inv14 - 0.5f * t[2];
            float t0y1 = t[1] * inv14 - 0.5f * t[3];
            float t0x2 = t[0] * inv14 + 0.5f * t[2];
            float t0y2 = t[1] * inv14 + 0.5f * t[3];
            float a2 = (t0x2 - t0x1) * (t0y2 - t0y1);

            float iou[2];
            #pragma unroll
            for (int b = 0; b < 2; b++) {
                const float* bb = p + 5 * b;
                float x1 = bb[0] * inv14 - 0.5f * bb[2];
                float y1 = bb[1] * inv14 - 0.5f * bb[3];
                float x2 = bb[0] * inv14 + 0.5f * bb[2];
                float y2 = bb[1] * inv14 + 0.5f * bb[3];
                float lx = fmaxf(x1, t0x1);
                float ly = fmaxf(y1, t0y1);
                float rx = fminf(x2, t0x2);
                float ry = fminf(y2, t0y2);
                float w = fmaxf(rx - lx, 0.0f);
                float h = fmaxf(ry - ly, 0.0f);
                float inter = w * h;
                float a1 = (x2 - x1) * (y2 - y1);
                iou[b] = inter / (a1 + a2 - inter);
            }

            int idx = (iou[1] > iou[0]) ? 1 : 0;
            float max_iou = fmaxf(iou[0], iou[1]);

            const float* pr = p + 5 * idx;
            const float* tr = t + 5 * idx;

            float dconf = pr[4] - max_iou;
            float contain = dconf * dconf;

            float dx = pr[0] - tr[0];
            float dy = pr[1] - tr[1];
            float dw = sqrtf(pr[2]) - sqrtf(tr[2]);
            float dh = sqrtf(pr[3]) - sqrtf(tr[3]);
            float loc = dx * dx + dy * dy + dw * dw + dh * dh;

            float oconf = idx ? p[4] : p[9];
            float not_contain = oconf * oconf;

            acc += coo * (5.0f * loc + 2.0f * contain + not_contain + cls)
                 + 0.5f * noo * noo_loss;

            // This warp is done reading its slice of the stage.
            __syncwarp();
            if (lane == 0)
                asm volatile("mbarrier.arrive.release.cta.shared::cta.b64 _, [%0];"
                             :: "r"(empty0 + 8u * stage) : "memory");
        }
    }

    // ---------------- Epilogue: block reduce + single packed atomic ----------
    #pragma unroll
    for (int o = 16; o > 0; o >>= 1)
        acc += __shfl_down_sync(0xffffffffu, acc, o);

    __shared__ float warpsum[8];
    if (wid < 8 && lane == 0) warpsum[wid] = acc;
    __syncthreads();

    if (tid == 0) {
        double s = 0.0;
        #pragma unroll
        for (int i = 0; i < 8; i++) s += (double)warpsum[i];

        // fixed-point contribution (all loss terms >= 0); block sums < 2^41,
        // grand total < 2^48 << 2^56, so bits [56,64) hold the block counter.
        unsigned long long q =
            (unsigned long long)__double2ll_rn(s * (double)(1 << SCALE_BITS));
        unsigned long long old =
            atomicAdd(&g_acc, q | (1ULL << CNT_SHIFT));

        if ((old >> CNT_SHIFT) == (unsigned long long)(GRID - 1)) {
            unsigned long long tot = (old & SUM_MASK) + q;
            out[0] = (float)((double)tot *
                             (1.0 / (double)(1 << SCALE_BITS)) * (double)invN);
            g_acc = 0ULL;   // reset for next graph replay
        }
    }
}

extern "C" void kernel_launch(void* const* d_in, const int* in_sizes, int n_in,
                              void* d_out, int out_size)
{
    const float* pred = (const float*)d_in[0];
    const float* tgt  = (const float*)d_in[1];
    float* out = (float*)d_out;

    int total = in_sizes[0];               // 2048*14*14*30
    int cells = total / CH;                // 401408 (= 3136 * 128 exactly)
    int N = cells / (14 * 14);             // 2048
    int ntiles = cells / CELLS_PER_TILE;   // 3136

    cudaFuncSetAttribute(yolo_fused_kernel,
                         cudaFuncAttributeMaxDynamicSharedMemorySize,
                         SMEM_BYTES);

    yolo_fused_kernel<<<GRID, TPB, SMEM_BYTES>>>(pred, tgt, out, ntiles,
                                                 1.0f / (float)N);
}